// round 1
// baseline (speedup 1.0000x reference)
#include <cuda_runtime.h>
#include <cstdint>

// Fused QKV projection + RoPE + transpose for
//   x: (4, 4096, 4096) f32, wq: (4096,4096), wk/wv: (1024,4096)
//   out = concat(q (4,32,4096,128), k (4,8,4096,128), v (4,8,4096,128)) f32
//
// GEMM: C[M=16384, N=6144] = X · W^T, TN layout (both K-contiguous).
// Tiles: BM=128, BN=128, BK=32; 8 warps (4x2), warp tile 32x64,
// mma.sync.m16n8k8 tf32 with cvt.rna rounding. cp.async double buffer.
// BN==HEAD_DIM==128 so each N-block is exactly one head of one tensor.

#define BM 128
#define BN 128
#define BK 32
#define KDIM 4096
#define NT (KDIM / BK)   // 128 k-tiles

__device__ __forceinline__ uint32_t f2tf(float f) {
    uint32_t u;
    asm("cvt.rna.tf32.f32 %0, %1;" : "=r"(u) : "f"(f));
    return u;
}

// swizzled word index within a [128][32] float tile:
// word = r*32 + ((c/4) ^ (r&7))*4 + (c&3)   (16B-chunk XOR swizzle)
__device__ __forceinline__ int swz(int r, int c) {
    return r * 32 + ((((c >> 2) ^ (r & 7)) << 2) | (c & 3));
}

__global__ __launch_bounds__(256) void qkv_rope_kernel(
    const float* __restrict__ x,
    const float* __restrict__ wq,
    const float* __restrict__ wk,
    const float* __restrict__ wv,
    const float* __restrict__ cosT,
    const float* __restrict__ sinT,
    float* __restrict__ out)
{
    extern __shared__ float smem[];   // As[2][4096] | Bs[2][4096]  = 64 KB
    float* As0 = smem;
    float* Bs0 = smem + 2 * BM * BK;

    const int tid = threadIdx.x;
    const int bn  = blockIdx.x;   // 0..47  (which 128-col head block)
    const int bm  = blockIdx.y;   // 0..127 (which 128-row block)

    // which weight tensor does this N-block belong to?
    const float* wptr;
    int kind;      // 0=q, 1=k, 2=v
    int hrow0;     // first row of W for this block (within its tensor)
    if (bn < 32)      { wptr = wq; kind = 0; hrow0 = bn * 128; }
    else if (bn < 40) { wptr = wk; kind = 1; hrow0 = (bn - 32) * 128; }
    else              { wptr = wv; kind = 2; hrow0 = (bn - 40) * 128; }

    const int m0 = bm * BM;

    const uint32_t sAs = (uint32_t)__cvta_generic_to_shared(As0);
    const uint32_t sBs = (uint32_t)__cvta_generic_to_shared(Bs0);

    const int warp  = tid >> 5;
    const int lane  = tid & 31;
    const int wm    = warp >> 1;    // 0..3
    const int wn    = warp & 1;     // 0..1
    const int group = lane >> 2;    // 0..7
    const int l4    = lane & 3;     // 0..3

    float acc[2][8][4];
    #pragma unroll
    for (int i = 0; i < 2; i++)
        #pragma unroll
        for (int j = 0; j < 8; j++)
            #pragma unroll
            for (int k = 0; k < 4; k++) acc[i][j][k] = 0.f;

    // ---- tile loader: 256 threads x 4 chunks of 16B each for A and B ----
    auto load_tile = [&](int kt, int buf) {
        const float* ga = x    + (long)m0    * KDIM + (long)kt * BK;
        const float* gb = wptr + (long)hrow0 * KDIM + (long)kt * BK;
        #pragma unroll
        for (int j = 0; j < 4; j++) {
            int c   = tid + j * 256;   // 0..1023
            int row = c >> 3;          // 0..127
            int kc  = c & 7;           // 16B chunk within the 32-float row
            int pc  = kc ^ (row & 7);  // swizzled physical chunk
            uint32_t da = sAs + (uint32_t)((buf * 4096 + row * 32 + pc * 4) * 4);
            const float* pa = ga + (long)row * KDIM + kc * 4;
            asm volatile("cp.async.cg.shared.global [%0], [%1], 16;\n"
                         :: "r"(da), "l"(pa));
            uint32_t db = sBs + (uint32_t)((buf * 4096 + row * 32 + pc * 4) * 4);
            const float* pb = gb + (long)row * KDIM + kc * 4;
            asm volatile("cp.async.cg.shared.global [%0], [%1], 16;\n"
                         :: "r"(db), "l"(pb));
        }
        asm volatile("cp.async.commit_group;\n");
    };

    load_tile(0, 0);

    for (int kt = 0; kt < NT; kt++) {
        if (kt + 1 < NT) {
            load_tile(kt + 1, (kt + 1) & 1);
            asm volatile("cp.async.wait_group 1;\n");
        } else {
            asm volatile("cp.async.wait_group 0;\n");
        }
        __syncthreads();

        const float* A = As0 + (kt & 1) * 4096;
        const float* B = Bs0 + (kt & 1) * 4096;

        #pragma unroll
        for (int ks = 0; ks < 4; ks++) {
            const int k0 = ks * 8;
            uint32_t af[2][4], bf[8][2];
            #pragma unroll
            for (int mm = 0; mm < 2; mm++) {
                int r = wm * 32 + mm * 16 + group;
                af[mm][0] = f2tf(A[swz(r,     k0 + l4)]);
                af[mm][1] = f2tf(A[swz(r + 8, k0 + l4)]);
                af[mm][2] = f2tf(A[swz(r,     k0 + l4 + 4)]);
                af[mm][3] = f2tf(A[swz(r + 8, k0 + l4 + 4)]);
            }
            #pragma unroll
            for (int nn = 0; nn < 8; nn++) {
                int r = wn * 64 + nn * 8 + group;
                bf[nn][0] = f2tf(B[swz(r, k0 + l4)]);
                bf[nn][1] = f2tf(B[swz(r, k0 + l4 + 4)]);
            }
            #pragma unroll
            for (int mm = 0; mm < 2; mm++)
                #pragma unroll
                for (int nn = 0; nn < 8; nn++) {
                    asm volatile(
                        "mma.sync.aligned.m16n8k8.row.col.f32.tf32.tf32.f32 "
                        "{%0,%1,%2,%3}, {%4,%5,%6,%7}, {%8,%9}, {%0,%1,%2,%3};\n"
                        : "+f"(acc[mm][nn][0]), "+f"(acc[mm][nn][1]),
                          "+f"(acc[mm][nn][2]), "+f"(acc[mm][nn][3])
                        : "r"(af[mm][0]), "r"(af[mm][1]),
                          "r"(af[mm][2]), "r"(af[mm][3]),
                          "r"(bf[nn][0]), "r"(bf[nn][1]));
                }
        }
        __syncthreads();
    }

    // ---- epilogue: RoPE (q,k) + transposed store ----
    const int  b      = m0 >> 12;       // batch (block never crosses batch)
    const int  s_base = m0 & 4095;
    long obase;
    if (kind == 0)      obase =              ((long)(b * 32 + bn)       ) * 4096L * 128L;
    else if (kind == 1) obase = 67108864L + ((long)(b * 8  + (bn - 32))) * 4096L * 128L;
    else                obase = 83886080L + ((long)(b * 8  + (bn - 40))) * 4096L * 128L;

    #pragma unroll
    for (int mm = 0; mm < 2; mm++) {
        #pragma unroll
        for (int half = 0; half < 2; half++) {
            const int s = s_base + wm * 32 + mm * 16 + group + half * 8;
            #pragma unroll
            for (int nn = 0; nn < 8; nn++) {
                const int d = wn * 64 + nn * 8 + 2 * l4;   // even
                float v0 = acc[mm][nn][half * 2 + 0];
                float v1 = acc[mm][nn][half * 2 + 1];
                if (kind != 2) {
                    const int i = d >> 1;
                    const float c  = __ldg(cosT + s * 64 + i);
                    const float sn = __ldg(sinT + s * 64 + i);
                    const float r0 = v0 * c - v1 * sn;
                    const float r1 = v0 * sn + v1 * c;
                    v0 = r0; v1 = r1;
                }
                *reinterpret_cast<float2*>(out + obase + (long)s * 128 + d) =
                    make_float2(v0, v1);
            }
        }
    }
}

extern "C" void kernel_launch(void* const* d_in, const int* in_sizes, int n_in,
                              void* d_out, int out_size)
{
    const float* x    = (const float*)d_in[0];
    const float* wq   = (const float*)d_in[1];
    const float* wk   = (const float*)d_in[2];
    const float* wv   = (const float*)d_in[3];
    const float* cosT = (const float*)d_in[4];
    const float* sinT = (const float*)d_in[5];
    float* out = (float*)d_out;

    (void)in_sizes; (void)n_in; (void)out_size;

    const int smem_bytes = 2 * 2 * BM * BK * (int)sizeof(float);  // 64 KB
    cudaFuncSetAttribute(qkv_rope_kernel,
                         cudaFuncAttributeMaxDynamicSharedMemorySize, smem_bytes);

    dim3 grid(48, 128);   // x: N-blocks (heads), y: M-blocks
    qkv_rope_kernel<<<grid, 256, smem_bytes>>>(x, wq, wk, wv, cosT, sinT, out);
}

// round 3
// speedup vs baseline: 2.7397x; 2.7397x over previous
#include <cuda_runtime.h>
#include <cuda_fp16.h>
#include <cstdint>

// Fused QKV projection + RoPE + transpose — fp16 HMMA (mma.sync m16n8k16).
// Pass 1: convert x (f32) and concat(wq,wk,wv) (f32) to f16 scratch.
// Pass 2: C[16384,6144] = Xh . Wh^T with 256x128x64 CTA tiles, 512 thr,
//         3-stage cp.async pipeline, ldmatrix fragment loads, fused RoPE.

#define BM 256
#define BN 128
#define NT 64                  // 4096 / 64 k-halves per tile
#define STAGES 3
#define A_BYTES (BM * 128)     // 32768 (256 rows x 64 halves x 2B)
#define B_BYTES (BN * 128)     // 16384
#define STAGE_BYTES (A_BYTES + B_BYTES)
#define SMEM_TOTAL (STAGES * STAGE_BYTES)   // 147456

__device__ __align__(16) __half X16[67108864];   // [16384][4096]
__device__ __align__(16) __half W16[25165824];   // [6144][4096] = wq|wk|wv

__global__ __launch_bounds__(256) void cvt_f32_f16(
    const float* __restrict__ src, __half* __restrict__ dst, int n)
{
    int i = (blockIdx.x * blockDim.x + threadIdx.x) * 8;
    if (i >= n) return;
    float4 f0 = *reinterpret_cast<const float4*>(src + i);
    float4 f1 = *reinterpret_cast<const float4*>(src + i + 4);
    union { uint4 u; __half2 h[4]; } pk;
    pk.h[0] = __floats2half2_rn(f0.x, f0.y);
    pk.h[1] = __floats2half2_rn(f0.z, f0.w);
    pk.h[2] = __floats2half2_rn(f1.x, f1.y);
    pk.h[3] = __floats2half2_rn(f1.z, f1.w);
    *reinterpret_cast<uint4*>(dst + i) = pk.u;
}

__device__ __forceinline__ uint32_t s2u(const void* p) {
    uint32_t a;
    asm("{ .reg .u64 t; cvta.to.shared.u64 t, %1; cvt.u32.u64 %0, t; }"
        : "=r"(a) : "l"(p));
    return a;
}

__global__ __launch_bounds__(512, 1) void qkv_hmma(
    const float* __restrict__ cosT,
    const float* __restrict__ sinT,
    float* __restrict__ out)
{
    extern __shared__ char smem[];
    const uint32_t sb = s2u(smem);
    const int tid  = threadIdx.x;
    const int bn   = blockIdx.x;      // 0..47 : head block (one head = 128 cols)
    const int bm   = blockIdx.y;      // 0..63 : 256-row block
    const int m0   = bm * BM;
    const int gn0  = bn * BN;         // row base in concatenated W16

    int kind;                         // 0=q,1=k,2=v (output placement only)
    if (bn < 32) kind = 0; else if (bn < 40) kind = 1; else kind = 2;

    const int warp = tid >> 5;
    const int lane = tid & 31;
    const int wm   = warp >> 1;       // 0..7  -> m = wm*32
    const int wn   = warp & 1;        // 0..1  -> n = wn*64
    const int q8   = lane >> 3;       // ldmatrix matrix id
    const int lr   = lane & 7;        // ldmatrix row within matrix

    float acc[2][8][4];
    #pragma unroll
    for (int i = 0; i < 2; i++)
        #pragma unroll
        for (int j = 0; j < 8; j++)
            #pragma unroll
            for (int k = 0; k < 4; k++) acc[i][j][k] = 0.f;

    // ---- loader: 3072 16B chunks/stage, 6 per thread ----
    auto load_tile = [&](int kt, int s) {
        const uint32_t base = sb + s * STAGE_BYTES;
        #pragma unroll
        for (int j = 0; j < 6; j++) {
            const int c = tid + j * 512;
            if (c < 2048) {                       // A: 256 rows x 8 chunks
                const int row = c >> 3, ch = c & 7;
                const int ph  = ch ^ (row & 7);
                const uint32_t dst = base + row * 128 + ph * 16;
                const __half* src = X16 + (size_t)(m0 + row) * 4096 + kt * 64 + ch * 8;
                asm volatile("cp.async.cg.shared.global [%0], [%1], 16;\n"
                             :: "r"(dst), "l"(src));
            } else {                              // B: 128 rows x 8 chunks
                const int cb = c - 2048;
                const int row = cb >> 3, ch = cb & 7;
                const int ph  = ch ^ (row & 7);
                const uint32_t dst = base + A_BYTES + row * 128 + ph * 16;
                const __half* src = W16 + (size_t)(gn0 + row) * 4096 + kt * 64 + ch * 8;
                asm volatile("cp.async.cg.shared.global [%0], [%1], 16;\n"
                             :: "r"(dst), "l"(src));
            }
        }
        asm volatile("cp.async.commit_group;\n");
    };

    load_tile(0, 0);
    load_tile(1, 1);

    for (int kt = 0; kt < NT; kt++) {
        if (kt + 2 < NT) load_tile(kt + 2, (kt + 2) % STAGES);
        else asm volatile("cp.async.commit_group;\n");   // keep group count uniform
        asm volatile("cp.async.wait_group 2;\n");
        __syncthreads();

        const uint32_t Ab = sb + (kt % STAGES) * STAGE_BYTES;
        const uint32_t Bb = Ab + A_BYTES;

        #pragma unroll
        for (int ks = 0; ks < 4; ks++) {
            // A fragments: 2 x ldmatrix.x4 (m16 x k16 each)
            uint32_t a[2][4];
            #pragma unroll
            for (int mm = 0; mm < 2; mm++) {
                const int row = wm * 32 + mm * 16 + (q8 & 1) * 8 + lr;
                const int ch  = ks * 2 + (q8 >> 1);
                const uint32_t addr = Ab + row * 128 + ((ch ^ (row & 7)) << 4);
                asm volatile("ldmatrix.sync.aligned.m8n8.x4.shared.b16 "
                             "{%0,%1,%2,%3}, [%4];"
                             : "=r"(a[mm][0]), "=r"(a[mm][1]),
                               "=r"(a[mm][2]), "=r"(a[mm][3]) : "r"(addr));
            }
            // B fragments: 4 x ldmatrix.x4 (two n8 x k16 frags each)
            uint32_t b[8][2];
            #pragma unroll
            for (int nb = 0; nb < 8; nb += 2) {
                const int row = wn * 64 + nb * 8 + (q8 >> 1) * 8 + lr;
                const int ch  = ks * 2 + (q8 & 1);
                const uint32_t addr = Bb + row * 128 + ((ch ^ (row & 7)) << 4);
                asm volatile("ldmatrix.sync.aligned.m8n8.x4.shared.b16 "
                             "{%0,%1,%2,%3}, [%4];"
                             : "=r"(b[nb][0]), "=r"(b[nb][1]),
                               "=r"(b[nb + 1][0]), "=r"(b[nb + 1][1]) : "r"(addr));
            }
            #pragma unroll
            for (int mm = 0; mm < 2; mm++)
                #pragma unroll
                for (int nn = 0; nn < 8; nn++) {
                    asm volatile(
                        "mma.sync.aligned.m16n8k16.row.col.f32.f16.f16.f32 "
                        "{%0,%1,%2,%3}, {%4,%5,%6,%7}, {%8,%9}, {%0,%1,%2,%3};\n"
                        : "+f"(acc[mm][nn][0]), "+f"(acc[mm][nn][1]),
                          "+f"(acc[mm][nn][2]), "+f"(acc[mm][nn][3])
                        : "r"(a[mm][0]), "r"(a[mm][1]),
                          "r"(a[mm][2]), "r"(a[mm][3]),
                          "r"(b[nn][0]), "r"(b[nn][1]));
                }
        }
        __syncthreads();
    }

    // ---- epilogue: RoPE (q,k) + transposed store ----
    const int bb     = m0 >> 12;
    const int s_base = m0 & 4095;
    long obase;
    if (kind == 0)      obase = ((long)(bb * 32 + bn)) << 19;
    else if (kind == 1) obase = 67108864L + (((long)(bb * 8 + bn - 32)) << 19);
    else                obase = 83886080L + (((long)(bb * 8 + bn - 40)) << 19);

    const int l4 = lane & 3;
    #pragma unroll
    for (int mm = 0; mm < 2; mm++) {
        #pragma unroll
        for (int h = 0; h < 2; h++) {
            const int s = s_base + wm * 32 + mm * 16 + h * 8 + (lane >> 2);
            #pragma unroll
            for (int nn = 0; nn < 8; nn++) {
                const int d = wn * 64 + nn * 8 + 2 * l4;
                float v0 = acc[mm][nn][2 * h + 0];
                float v1 = acc[mm][nn][2 * h + 1];
                if (kind != 2) {
                    const int i = d >> 1;
                    const float c  = __ldg(cosT + s * 64 + i);
                    const float sn = __ldg(sinT + s * 64 + i);
                    const float r0 = v0 * c - v1 * sn;
                    const float r1 = v0 * sn + v1 * c;
                    v0 = r0; v1 = r1;
                }
                *reinterpret_cast<float2*>(out + obase + (long)s * 128 + d) =
                    make_float2(v0, v1);
            }
        }
    }
}

extern "C" void kernel_launch(void* const* d_in, const int* in_sizes, int n_in,
                              void* d_out, int out_size)
{
    (void)in_sizes; (void)n_in; (void)out_size;
    const float* x  = (const float*)d_in[0];
    const float* wq = (const float*)d_in[1];
    const float* wk = (const float*)d_in[2];
    const float* wv = (const float*)d_in[3];

    __half *xh = nullptr, *wh = nullptr;
    cudaGetSymbolAddress((void**)&xh, X16);
    cudaGetSymbolAddress((void**)&wh, W16);

    cvt_f32_f16<<<32768, 256>>>(x,  xh, 67108864);
    cvt_f32_f16<<<8192,  256>>>(wq, wh,             16777216);
    cvt_f32_f16<<<2048,  256>>>(wk, wh + 16777216,  4194304);
    cvt_f32_f16<<<2048,  256>>>(wv, wh + 20971520,  4194304);

    cudaFuncSetAttribute(qkv_hmma, cudaFuncAttributeMaxDynamicSharedMemorySize,
                         SMEM_TOTAL);
    dim3 grid(48, 64);
    qkv_hmma<<<grid, 512, SMEM_TOTAL>>>((const float*)d_in[4],
                                        (const float*)d_in[5],
                                        (float*)d_out);
}

// round 5
// speedup vs baseline: 2.7503x; 1.0039x over previous
#include <cuda_runtime.h>
#include <cuda_fp16.h>
#include <cstdint>

// Fused QKV projection + RoPE + transpose — fp16 HMMA m16n8k16.
// Pass 1: f32 -> f16 scratch (X16, W16 = wq|wk|wv concatenated).
// Pass 2: C[16384,6144] = Xh . Wh^T. CTA tile 256x128xK64, 256 threads,
//         8 warps with 64x64 warp tiles (minimal smem crossbar traffic),
//         4-stage cp.async pipeline, ldmatrix, fused RoPE epilogue.

#define BM 256
#define BN 128
#define NT 64                  // 4096/64 k-slabs
#define STAGES 4
#define A_BYTES (BM * 128)     // 32768
#define B_BYTES (BN * 128)     // 16384
#define STAGE_BYTES (A_BYTES + B_BYTES)
#define SMEM_TOTAL (STAGES * STAGE_BYTES)   // 196608

__device__ __align__(16) __half X16[67108864];   // [16384][4096]
__device__ __align__(16) __half W16[25165824];   // [6144][4096]

__global__ __launch_bounds__(256) void cvt_f32_f16(
    const float* __restrict__ src, __half* __restrict__ dst, int n)
{
    int i = (blockIdx.x * blockDim.x + threadIdx.x) * 8;
    if (i >= n) return;
    float4 f0 = __ldcs(reinterpret_cast<const float4*>(src + i));
    float4 f1 = __ldcs(reinterpret_cast<const float4*>(src + i + 4));
    union { uint4 u; __half2 h[4]; } pk;
    pk.h[0] = __floats2half2_rn(f0.x, f0.y);
    pk.h[1] = __floats2half2_rn(f0.z, f0.w);
    pk.h[2] = __floats2half2_rn(f1.x, f1.y);
    pk.h[3] = __floats2half2_rn(f1.z, f1.w);
    *reinterpret_cast<uint4*>(dst + i) = pk.u;
}

__device__ __forceinline__ uint32_t s2u(const void* p) {
    uint32_t a;
    asm("{ .reg .u64 t; cvta.to.shared.u64 t, %1; cvt.u32.u64 %0, t; }"
        : "=r"(a) : "l"(p));
    return a;
}

__global__ __launch_bounds__(256, 1) void qkv_hmma(
    const float* __restrict__ cosT,
    const float* __restrict__ sinT,
    float* __restrict__ out)
{
    extern __shared__ char smem[];
    const uint32_t sb = s2u(smem);
    const int tid = threadIdx.x;
    const int bn  = blockIdx.x;       // 0..47 head block
    const int bm  = blockIdx.y;       // 0..63 256-row block
    const int m0  = bm * BM;
    const int gn0 = bn * BN;

    int kind;
    if (bn < 32) kind = 0; else if (bn < 40) kind = 1; else kind = 2;

    const int warp = tid >> 5;
    const int lane = tid & 31;
    const int wm   = warp >> 1;       // 0..3 -> m = wm*64
    const int wn   = warp & 1;        // 0..1 -> n = wn*64
    const int q8   = lane >> 3;
    const int lr   = lane & 7;

    float acc[4][8][4];
    #pragma unroll
    for (int i = 0; i < 4; i++)
        #pragma unroll
        for (int j = 0; j < 8; j++)
            #pragma unroll
            for (int k = 0; k < 4; k++) acc[i][j][k] = 0.f;

    // ---- loader: 3072 chunks of 16B per stage, 12 per thread ----
    auto load_tile = [&](int kt, int s) {
        const uint32_t base = sb + s * STAGE_BYTES;
        #pragma unroll
        for (int j = 0; j < 12; j++) {
            const int c = tid + j * 256;
            if (c < 2048) {                          // A: 256 rows x 8 chunks
                const int row = c >> 3, ch = c & 7;
                const uint32_t dst = base + row * 128 + ((ch ^ (row & 7)) << 4);
                const __half* src = X16 + (size_t)(m0 + row) * 4096 + kt * 64 + ch * 8;
                asm volatile("cp.async.cg.shared.global [%0], [%1], 16;\n"
                             :: "r"(dst), "l"(src));
            } else {                                 // B: 128 rows x 8 chunks
                const int cb = c - 2048;
                const int row = cb >> 3, ch = cb & 7;
                const uint32_t dst = base + A_BYTES + row * 128 + ((ch ^ (row & 7)) << 4);
                const __half* src = W16 + (size_t)(gn0 + row) * 4096 + kt * 64 + ch * 8;
                asm volatile("cp.async.cg.shared.global [%0], [%1], 16;\n"
                             :: "r"(dst), "l"(src));
            }
        }
        asm volatile("cp.async.commit_group;\n");
    };

    load_tile(0, 0);
    load_tile(1, 1);
    load_tile(2, 2);

    for (int kt = 0; kt < NT; kt++) {
        if (kt + 3 < NT) load_tile(kt + 3, (kt + 3) & 3);
        else asm volatile("cp.async.commit_group;\n");
        asm volatile("cp.async.wait_group 3;\n");
        __syncthreads();

        const uint32_t Ab = sb + (kt & 3) * STAGE_BYTES;
        const uint32_t Bb = Ab + A_BYTES;

        #pragma unroll
        for (int ks = 0; ks < 4; ks++) {
            uint32_t a[4][4];
            #pragma unroll
            for (int mm = 0; mm < 4; mm++) {
                const int row = wm * 64 + mm * 16 + (q8 & 1) * 8 + lr;
                const int ch  = ks * 2 + (q8 >> 1);
                const uint32_t addr = Ab + row * 128 + ((ch ^ (row & 7)) << 4);
                asm volatile("ldmatrix.sync.aligned.m8n8.x4.shared.b16 "
                             "{%0,%1,%2,%3}, [%4];"
                             : "=r"(a[mm][0]), "=r"(a[mm][1]),
                               "=r"(a[mm][2]), "=r"(a[mm][3]) : "r"(addr));
            }
            uint32_t b[8][2];
            #pragma unroll
            for (int nb = 0; nb < 8; nb += 2) {
                const int row = wn * 64 + nb * 8 + (q8 >> 1) * 8 + lr;
                const int ch  = ks * 2 + (q8 & 1);
                const uint32_t addr = Bb + row * 128 + ((ch ^ (row & 7)) << 4);
                asm volatile("ldmatrix.sync.aligned.m8n8.x4.shared.b16 "
                             "{%0,%1,%2,%3}, [%4];"
                             : "=r"(b[nb][0]), "=r"(b[nb][1]),
                               "=r"(b[nb + 1][0]), "=r"(b[nb + 1][1]) : "r"(addr));
            }
            #pragma unroll
            for (int mm = 0; mm < 4; mm++)
                #pragma unroll
                for (int nn = 0; nn < 8; nn++) {
                    asm volatile(
                        "mma.sync.aligned.m16n8k16.row.col.f32.f16.f16.f32 "
                        "{%0,%1,%2,%3}, {%4,%5,%6,%7}, {%8,%9}, {%0,%1,%2,%3};\n"
                        : "+f"(acc[mm][nn][0]), "+f"(acc[mm][nn][1]),
                          "+f"(acc[mm][nn][2]), "+f"(acc[mm][nn][3])
                        : "r"(a[mm][0]), "r"(a[mm][1]),
                          "r"(a[mm][2]), "r"(a[mm][3]),
                          "r"(b[nn][0]), "r"(b[nn][1]));
                }
        }
        __syncthreads();
    }

    // ---- epilogue: RoPE (q,k) + transposed store ----
    const int bb     = m0 >> 12;
    const int s_base = m0 & 4095;
    long obase;
    if (kind == 0)      obase = ((long)(bb * 32 + bn)) << 19;
    else if (kind == 1) obase = 67108864L + (((long)(bb * 8 + bn - 32)) << 19);
    else                obase = 83886080L + (((long)(bb * 8 + bn - 40)) << 19);

    const int l4 = lane & 3;
    #pragma unroll
    for (int mm = 0; mm < 4; mm++) {
        #pragma unroll
        for (int h = 0; h < 2; h++) {
            const int s = s_base + wm * 64 + mm * 16 + h * 8 + (lane >> 2);
            #pragma unroll
            for (int nn = 0; nn < 8; nn++) {
                const int d = wn * 64 + nn * 8 + 2 * l4;
                float v0 = acc[mm][nn][2 * h + 0];
                float v1 = acc[mm][nn][2 * h + 1];
                if (kind != 2) {
                    const int i = d >> 1;
                    const float c  = __ldg(cosT + s * 64 + i);
                    const float sn = __ldg(sinT + s * 64 + i);
                    const float r0 = v0 * c - v1 * sn;
                    const float r1 = v0 * sn + v1 * c;
                    v0 = r0; v1 = r1;
                }
                *reinterpret_cast<float2*>(out + obase + (long)s * 128 + d) =
                    make_float2(v0, v1);
            }
        }
    }
}

extern "C" void kernel_launch(void* const* d_in, const int* in_sizes, int n_in,
                              void* d_out, int out_size)
{
    (void)in_sizes; (void)n_in; (void)out_size;
    const float* x  = (const float*)d_in[0];
    const float* wq = (const float*)d_in[1];
    const float* wk = (const float*)d_in[2];
    const float* wv = (const float*)d_in[3];

    __half *xh = nullptr, *wh = nullptr;
    cudaGetSymbolAddress((void**)&xh, X16);
    cudaGetSymbolAddress((void**)&wh, W16);

    cvt_f32_f16<<<32768, 256>>>(x,  xh, 67108864);
    cvt_f32_f16<<<8192,  256>>>(wq, wh,             16777216);
    cvt_f32_f16<<<2048,  256>>>(wk, wh + 16777216,  4194304);
    cvt_f32_f16<<<2048,  256>>>(wv, wh + 20971520,  4194304);

    cudaFuncSetAttribute(qkv_hmma, cudaFuncAttributeMaxDynamicSharedMemorySize,
                         SMEM_TOTAL);
    dim3 grid(48, 64);
    qkv_hmma<<<grid, 256, SMEM_TOTAL>>>((const float*)d_in[4],
                                        (const float*)d_in[5],
                                        (float*)d_out);
}

// round 8
// speedup vs baseline: 2.8719x; 1.0442x over previous
#include <cuda_runtime.h>
#include <cuda_fp16.h>
#include <cstdint>

// Fused QKV projection + RoPE + transpose — fp16 HMMA m16n8k16.
// Pass 1 (single kernel): f32 -> f16 scratch (X16, W16 = wq|wk|wv concat).
// Pass 2: C[16384,6144] = Xh . Wh^T. CTA 256x128xK64, 256 thr, 8 warps,
//         64x64 warp tiles, 4-stage cp.async ring with ONE barrier per
//         k-tile (load for kt+3 issued right after the barrier), ldmatrix,
//         fused RoPE epilogue.
// (Resubmit of round-6 kernel — previous bench aborted on container infra.)

#define BM 256
#define BN 128
#define NT 64
#define STAGES 4
#define A_BYTES (BM * 128)
#define B_BYTES (BN * 128)
#define STAGE_BYTES (A_BYTES + B_BYTES)
#define SMEM_TOTAL (STAGES * STAGE_BYTES)   // 196608

__device__ __align__(16) __half X16[67108864];   // [16384][4096]
__device__ __align__(16) __half W16[25165824];   // [6144][4096]

// one kernel converts all four tensors (keeps launches/replay at 2 so ncu
// lands on the GEMM)
__global__ __launch_bounds__(256) void cvt_all(
    const float* __restrict__ x,  const float* __restrict__ wq,
    const float* __restrict__ wk, const float* __restrict__ wv)
{
    const size_t i = ((size_t)blockIdx.x * 256 + threadIdx.x) * 8;
    const float* src;
    __half* dst;
    if (i < 67108864UL)       { src = x  + i;               dst = X16 + i; }
    else if (i < 83886080UL)  { src = wq + (i - 67108864);  dst = W16 + (i - 67108864); }
    else if (i < 88080384UL)  { src = wk + (i - 83886080);  dst = W16 + 16777216 + (i - 83886080); }
    else                      { src = wv + (i - 88080384);  dst = W16 + 20971520 + (i - 88080384); }
    float4 f0 = __ldcs(reinterpret_cast<const float4*>(src));
    float4 f1 = __ldcs(reinterpret_cast<const float4*>(src) + 1);
    union { uint4 u; __half2 h[4]; } pk;
    pk.h[0] = __floats2half2_rn(f0.x, f0.y);
    pk.h[1] = __floats2half2_rn(f0.z, f0.w);
    pk.h[2] = __floats2half2_rn(f1.x, f1.y);
    pk.h[3] = __floats2half2_rn(f1.z, f1.w);
    *reinterpret_cast<uint4*>(dst) = pk.u;
}

__device__ __forceinline__ uint32_t s2u(const void* p) {
    uint32_t a;
    asm("{ .reg .u64 t; cvta.to.shared.u64 t, %1; cvt.u32.u64 %0, t; }"
        : "=r"(a) : "l"(p));
    return a;
}

__global__ __launch_bounds__(256, 1) void qkv_hmma(
    const float* __restrict__ cosT,
    const float* __restrict__ sinT,
    float* __restrict__ out)
{
    extern __shared__ char smem[];
    const uint32_t sb = s2u(smem);
    const int tid = threadIdx.x;
    const int bn  = blockIdx.x;
    const int bm  = blockIdx.y;
    const int m0  = bm * BM;
    const int gn0 = bn * BN;

    int kind;
    if (bn < 32) kind = 0; else if (bn < 40) kind = 1; else kind = 2;

    const int warp = tid >> 5;
    const int lane = tid & 31;
    const int wm   = warp >> 1;
    const int wn   = warp & 1;
    const int q8   = lane >> 3;
    const int lr   = lane & 7;

    float acc[4][8][4];
    #pragma unroll
    for (int i = 0; i < 4; i++)
        #pragma unroll
        for (int j = 0; j < 8; j++)
            #pragma unroll
            for (int k = 0; k < 4; k++) acc[i][j][k] = 0.f;

    auto load_tile = [&](int kt, int s) {
        const uint32_t base = sb + s * STAGE_BYTES;
        #pragma unroll
        for (int j = 0; j < 12; j++) {
            const int c = tid + j * 256;
            if (c < 2048) {
                const int row = c >> 3, ch = c & 7;
                const uint32_t dst = base + row * 128 + ((ch ^ (row & 7)) << 4);
                const __half* src = X16 + (size_t)(m0 + row) * 4096 + kt * 64 + ch * 8;
                asm volatile("cp.async.cg.shared.global [%0], [%1], 16;\n"
                             :: "r"(dst), "l"(src));
            } else {
                const int cb = c - 2048;
                const int row = cb >> 3, ch = cb & 7;
                const uint32_t dst = base + A_BYTES + row * 128 + ((ch ^ (row & 7)) << 4);
                const __half* src = W16 + (size_t)(gn0 + row) * 4096 + kt * 64 + ch * 8;
                asm volatile("cp.async.cg.shared.global [%0], [%1], 16;\n"
                             :: "r"(dst), "l"(src));
            }
        }
        asm volatile("cp.async.commit_group;\n");
    };

    load_tile(0, 0);
    load_tile(1, 1);
    load_tile(2, 2);

    for (int kt = 0; kt < NT; kt++) {
        asm volatile("cp.async.wait_group 2;\n");
        __syncthreads();
        // safe: buffer (kt+3)&3 == (kt-1)&3 was fully consumed before the
        // barrier above (all warps finished compute(kt-1))
        if (kt + 3 < NT) load_tile(kt + 3, (kt + 3) & 3);
        else asm volatile("cp.async.commit_group;\n");

        const uint32_t Ab = sb + (kt & 3) * STAGE_BYTES;
        const uint32_t Bb = Ab + A_BYTES;

        #pragma unroll
        for (int ks = 0; ks < 4; ks++) {
            uint32_t a[4][4];
            #pragma unroll
            for (int mm = 0; mm < 4; mm++) {
                const int row = wm * 64 + mm * 16 + (q8 & 1) * 8 + lr;
                const int ch  = ks * 2 + (q8 >> 1);
                const uint32_t addr = Ab + row * 128 + ((ch ^ (row & 7)) << 4);
                asm volatile("ldmatrix.sync.aligned.m8n8.x4.shared.b16 "
                             "{%0,%1,%2,%3}, [%4];"
                             : "=r"(a[mm][0]), "=r"(a[mm][1]),
                               "=r"(a[mm][2]), "=r"(a[mm][3]) : "r"(addr));
            }
            uint32_t b[8][2];
            #pragma unroll
            for (int nb = 0; nb < 8; nb += 2) {
                const int row = wn * 64 + nb * 8 + (q8 >> 1) * 8 + lr;
                const int ch  = ks * 2 + (q8 & 1);
                const uint32_t addr = Bb + row * 128 + ((ch ^ (row & 7)) << 4);
                asm volatile("ldmatrix.sync.aligned.m8n8.x4.shared.b16 "
                             "{%0,%1,%2,%3}, [%4];"
                             : "=r"(b[nb][0]), "=r"(b[nb][1]),
                               "=r"(b[nb + 1][0]), "=r"(b[nb + 1][1]) : "r"(addr));
            }
            #pragma unroll
            for (int mm = 0; mm < 4; mm++)
                #pragma unroll
                for (int nn = 0; nn < 8; nn++) {
                    asm volatile(
                        "mma.sync.aligned.m16n8k16.row.col.f32.f16.f16.f32 "
                        "{%0,%1,%2,%3}, {%4,%5,%6,%7}, {%8,%9}, {%0,%1,%2,%3};\n"
                        : "+f"(acc[mm][nn][0]), "+f"(acc[mm][nn][1]),
                          "+f"(acc[mm][nn][2]), "+f"(acc[mm][nn][3])
                        : "r"(a[mm][0]), "r"(a[mm][1]),
                          "r"(a[mm][2]), "r"(a[mm][3]),
                          "r"(b[nn][0]), "r"(b[nn][1]));
                }
        }
    }

    // ---- epilogue: RoPE (q,k) + transposed store ----
    const int bb     = m0 >> 12;
    const int s_base = m0 & 4095;
    long obase;
    if (kind == 0)      obase = ((long)(bb * 32 + bn)) << 19;
    else if (kind == 1) obase = 67108864L + (((long)(bb * 8 + bn - 32)) << 19);
    else                obase = 83886080L + (((long)(bb * 8 + bn - 40)) << 19);

    const int l4 = lane & 3;
    #pragma unroll
    for (int mm = 0; mm < 4; mm++) {
        #pragma unroll
        for (int h = 0; h < 2; h++) {
            const int s = s_base + wm * 64 + mm * 16 + h * 8 + (lane >> 2);
            #pragma unroll
            for (int nn = 0; nn < 8; nn++) {
                const int d = wn * 64 + nn * 8 + 2 * l4;
                float v0 = acc[mm][nn][2 * h + 0];
                float v1 = acc[mm][nn][2 * h + 1];
                if (kind != 2) {
                    const int i = d >> 1;
                    const float c  = __ldg(cosT + s * 64 + i);
                    const float sn = __ldg(sinT + s * 64 + i);
                    const float r0 = v0 * c - v1 * sn;
                    const float r1 = v0 * sn + v1 * c;
                    v0 = r0; v1 = r1;
                }
                *reinterpret_cast<float2*>(out + obase + (long)s * 128 + d) =
                    make_float2(v0, v1);
            }
        }
    }
}

extern "C" void kernel_launch(void* const* d_in, const int* in_sizes, int n_in,
                              void* d_out, int out_size)
{
    (void)in_sizes; (void)n_in; (void)out_size;

    cvt_all<<<45056, 256>>>((const float*)d_in[0], (const float*)d_in[1],
                            (const float*)d_in[2], (const float*)d_in[3]);

    cudaFuncSetAttribute(qkv_hmma, cudaFuncAttributeMaxDynamicSharedMemorySize,
                         SMEM_TOTAL);
    dim3 grid(48, 64);
    qkv_hmma<<<grid, 256, SMEM_TOTAL>>>((const float*)d_in[4],
                                        (const float*)d_in[5],
                                        (float*)d_out);
}

// round 10
// speedup vs baseline: 3.2177x; 1.1204x over previous
#include <cuda_runtime.h>
#include <cuda_fp16.h>
#include <cstdint>

// Fused QKV projection + RoPE + transpose — fp16 HMMA m16n8k16.
// Pass 1 (single kernel): f32 -> f16 scratch (X16, W16 = wq|wk|wv concat).
// Pass 2: C[16384,6144] = Xh . Wh^T. CTA 128x128xK64, 256 thr, 8 warps,
//         32x64 warp tiles (acc=64 regs -> 2 CTAs/SM for latency hiding),
//         3-stage cp.async ring, one barrier per k-tile, ldmatrix,
//         fused RoPE epilogue.
// (Resubmit — previous bench aborted on container infra.)

#define BM 128
#define BN 128
#define NT 64
#define STAGES 3
#define A_BYTES (BM * 128)     // 16384
#define B_BYTES (BN * 128)     // 16384
#define STAGE_BYTES (A_BYTES + B_BYTES)
#define SMEM_TOTAL (STAGES * STAGE_BYTES)   // 98304

__device__ __align__(16) __half X16[67108864];   // [16384][4096]
__device__ __align__(16) __half W16[25165824];   // [6144][4096]

__global__ __launch_bounds__(256) void cvt_all(
    const float* __restrict__ x,  const float* __restrict__ wq,
    const float* __restrict__ wk, const float* __restrict__ wv)
{
    const size_t i = ((size_t)blockIdx.x * 256 + threadIdx.x) * 8;
    const float* src;
    __half* dst;
    if (i < 67108864UL)       { src = x  + i;               dst = X16 + i; }
    else if (i < 83886080UL)  { src = wq + (i - 67108864);  dst = W16 + (i - 67108864); }
    else if (i < 88080384UL)  { src = wk + (i - 83886080);  dst = W16 + 16777216 + (i - 83886080); }
    else                      { src = wv + (i - 88080384);  dst = W16 + 20971520 + (i - 88080384); }
    float4 f0 = __ldcs(reinterpret_cast<const float4*>(src));
    float4 f1 = __ldcs(reinterpret_cast<const float4*>(src) + 1);
    union { uint4 u; __half2 h[4]; } pk;
    pk.h[0] = __floats2half2_rn(f0.x, f0.y);
    pk.h[1] = __floats2half2_rn(f0.z, f0.w);
    pk.h[2] = __floats2half2_rn(f1.x, f1.y);
    pk.h[3] = __floats2half2_rn(f1.z, f1.w);
    *reinterpret_cast<uint4*>(dst) = pk.u;
}

__device__ __forceinline__ uint32_t s2u(const void* p) {
    uint32_t a;
    asm("{ .reg .u64 t; cvta.to.shared.u64 t, %1; cvt.u32.u64 %0, t; }"
        : "=r"(a) : "l"(p));
    return a;
}

__global__ __launch_bounds__(256, 2) void qkv_hmma(
    const float* __restrict__ cosT,
    const float* __restrict__ sinT,
    float* __restrict__ out)
{
    extern __shared__ char smem[];
    const uint32_t sb = s2u(smem);
    const int tid = threadIdx.x;
    const int bn  = blockIdx.x;       // 0..47 head block
    const int bm  = blockIdx.y;       // 0..127 row block
    const int m0  = bm * BM;
    const int gn0 = bn * BN;

    int kind;
    if (bn < 32) kind = 0; else if (bn < 40) kind = 1; else kind = 2;

    const int warp = tid >> 5;
    const int lane = tid & 31;
    const int wm   = warp >> 1;       // 0..3 -> m = wm*32
    const int wn   = warp & 1;        // 0..1 -> n = wn*64
    const int q8   = lane >> 3;
    const int lr   = lane & 7;

    float acc[2][8][4];
    #pragma unroll
    for (int i = 0; i < 2; i++)
        #pragma unroll
        for (int j = 0; j < 8; j++)
            #pragma unroll
            for (int k = 0; k < 4; k++) acc[i][j][k] = 0.f;

    // ---- loader: 2048 chunks of 16B per stage, 8 per thread ----
    auto load_tile = [&](int kt, int s) {
        const uint32_t base = sb + s * STAGE_BYTES;
        #pragma unroll
        for (int j = 0; j < 8; j++) {
            const int c = tid + j * 256;
            if (c < 1024) {                          // A: 128 rows x 8 chunks
                const int row = c >> 3, ch = c & 7;
                const uint32_t dst = base + row * 128 + ((ch ^ (row & 7)) << 4);
                const __half* src = X16 + (size_t)(m0 + row) * 4096 + kt * 64 + ch * 8;
                asm volatile("cp.async.cg.shared.global [%0], [%1], 16;\n"
                             :: "r"(dst), "l"(src));
            } else {                                 // B: 128 rows x 8 chunks
                const int cb = c - 1024;
                const int row = cb >> 3, ch = cb & 7;
                const uint32_t dst = base + A_BYTES + row * 128 + ((ch ^ (row & 7)) << 4);
                const __half* src = W16 + (size_t)(gn0 + row) * 4096 + kt * 64 + ch * 8;
                asm volatile("cp.async.cg.shared.global [%0], [%1], 16;\n"
                             :: "r"(dst), "l"(src));
            }
        }
        asm volatile("cp.async.commit_group;\n");
    };

    load_tile(0, 0);
    load_tile(1, 1);

    int sl = 2;                       // next stage slot to fill
    for (int kt = 0; kt < NT; kt++) {
        asm volatile("cp.async.wait_group 1;\n");
        __syncthreads();
        // slot sl == (kt-1)%3: its consumer finished before the barrier. Safe.
        if (kt + 2 < NT) load_tile(kt + 2, sl);
        else asm volatile("cp.async.commit_group;\n");
        sl = (sl == 2) ? 0 : sl + 1;

        const uint32_t Ab = sb + (kt % 3) * STAGE_BYTES;
        const uint32_t Bb = Ab + A_BYTES;

        #pragma unroll
        for (int ks = 0; ks < 4; ks++) {
            uint32_t a[2][4];
            #pragma unroll
            for (int mm = 0; mm < 2; mm++) {
                const int row = wm * 32 + mm * 16 + (q8 & 1) * 8 + lr;
                const int ch  = ks * 2 + (q8 >> 1);
                const uint32_t addr = Ab + row * 128 + ((ch ^ (row & 7)) << 4);
                asm volatile("ldmatrix.sync.aligned.m8n8.x4.shared.b16 "
                             "{%0,%1,%2,%3}, [%4];"
                             : "=r"(a[mm][0]), "=r"(a[mm][1]),
                               "=r"(a[mm][2]), "=r"(a[mm][3]) : "r"(addr));
            }
            uint32_t b[8][2];
            #pragma unroll
            for (int nb = 0; nb < 8; nb += 2) {
                const int row = wn * 64 + nb * 8 + (q8 >> 1) * 8 + lr;
                const int ch  = ks * 2 + (q8 & 1);
                const uint32_t addr = Bb + row * 128 + ((ch ^ (row & 7)) << 4);
                asm volatile("ldmatrix.sync.aligned.m8n8.x4.shared.b16 "
                             "{%0,%1,%2,%3}, [%4];"
                             : "=r"(b[nb][0]), "=r"(b[nb][1]),
                               "=r"(b[nb + 1][0]), "=r"(b[nb + 1][1]) : "r"(addr));
            }
            #pragma unroll
            for (int mm = 0; mm < 2; mm++)
                #pragma unroll
                for (int nn = 0; nn < 8; nn++) {
                    asm volatile(
                        "mma.sync.aligned.m16n8k16.row.col.f32.f16.f16.f32 "
                        "{%0,%1,%2,%3}, {%4,%5,%6,%7}, {%8,%9}, {%0,%1,%2,%3};\n"
                        : "+f"(acc[mm][nn][0]), "+f"(acc[mm][nn][1]),
                          "+f"(acc[mm][nn][2]), "+f"(acc[mm][nn][3])
                        : "r"(a[mm][0]), "r"(a[mm][1]),
                          "r"(a[mm][2]), "r"(a[mm][3]),
                          "r"(b[nn][0]), "r"(b[nn][1]));
                }
        }
    }

    // ---- epilogue: RoPE (q,k) + transposed store ----
    const int bb     = m0 >> 12;
    const int s_base = m0 & 4095;
    long obase;
    if (kind == 0)      obase = ((long)(bb * 32 + bn)) << 19;
    else if (kind == 1) obase = 67108864L + (((long)(bb * 8 + bn - 32)) << 19);
    else                obase = 83886080L + (((long)(bb * 8 + bn - 40)) << 19);

    const int l4 = lane & 3;
    #pragma unroll
    for (int mm = 0; mm < 2; mm++) {
        #pragma unroll
        for (int h = 0; h < 2; h++) {
            const int s = s_base + wm * 32 + mm * 16 + h * 8 + (lane >> 2);
            #pragma unroll
            for (int nn = 0; nn < 8; nn++) {
                const int d = wn * 64 + nn * 8 + 2 * l4;
                float v0 = acc[mm][nn][2 * h + 0];
                float v1 = acc[mm][nn][2 * h + 1];
                if (kind != 2) {
                    const int i = d >> 1;
                    const float c  = __ldg(cosT + s * 64 + i);
                    const float sn = __ldg(sinT + s * 64 + i);
                    const float r0 = v0 * c - v1 * sn;
                    const float r1 = v0 * sn + v1 * c;
                    v0 = r0; v1 = r1;
                }
                *reinterpret_cast<float2*>(out + obase + (long)s * 128 + d) =
                    make_float2(v0, v1);
            }
        }
    }
}

extern "C" void kernel_launch(void* const* d_in, const int* in_sizes, int n_in,
                              void* d_out, int out_size)
{
    (void)in_sizes; (void)n_in; (void)out_size;

    cvt_all<<<45056, 256>>>((const float*)d_in[0], (const float*)d_in[1],
                            (const float*)d_in[2], (const float*)d_in[3]);

    cudaFuncSetAttribute(qkv_hmma, cudaFuncAttributeMaxDynamicSharedMemorySize,
                         SMEM_TOTAL);
    dim3 grid(48, 128);
    qkv_hmma<<<grid, 256, SMEM_TOTAL>>>((const float*)d_in[4],
                                        (const float*)d_in[5],
                                        (float*)d_out);
}